// round 13
// baseline (speedup 1.0000x reference)
#include <cuda_runtime.h>

// Problem constants
#define NB_   1024
#define NE_   128
#define NAO_  128
#define NMO_  128
#define NC_   32
#define DD_   64

// smem strides (in floats) chosen for alignment + bank behavior
#define XS_STRIDE 128   // x tile, float4 loads, broadcast access -> no pad needed
#define WT_STRIDE 132   // transposed W, float4 aligned (132 % 4 == 0)
#define MO_STRIDE 130   // mo tile, even (float2-capable), mild conflicts on gather

// floats: xs 128*128=16384, wt 128*132=16896, mo 128*130=16640,
//         cfg (as int) 32*64=2048, dets 32   => 52000 floats = 208000 bytes
#define SMEM_BYTES (52000 * 4)

__global__ __launch_bounds__(256, 1)
void wavenet_det_kernel(const float* __restrict__ x,
                        const float* __restrict__ W_mo,
                        const float* __restrict__ W_ci,
                        const int*   __restrict__ configs,
                        float*       __restrict__ out)
{
    extern __shared__ float sm[];
    float* xs   = sm;                               // [128][128]
    float* wt   = xs + NE_ * XS_STRIDE;             // [n][m] transposed W, [128][132]
    float* mo   = wt + NAO_ * WT_STRIDE;            // [e][m], [128][130]
    int*   cfg  = (int*)(mo + NE_ * MO_STRIDE);     // [32][64]
    float* dets = (float*)(cfg + NC_ * DD_);        // [32]

    const int tid = threadIdx.x;
    const int b   = blockIdx.x;

    // ---- stage inputs ------------------------------------------------------
    {
        const float4* xb4 = (const float4*)(x + (size_t)b * NE_ * NAO_);
        float4* xs4 = (float4*)xs;
        #pragma unroll 4
        for (int i = tid; i < NE_ * NAO_ / 4; i += 256) xs4[i] = xb4[i];

        // transposed W: wt[n][m] = W_mo[m][n]   (coalesced global reads)
        for (int i = tid; i < NMO_ * NAO_; i += 256) {
            int m = i >> 7, n = i & 127;
            wt[n * WT_STRIDE + m] = W_mo[i];
        }
        for (int i = tid; i < NC_ * DD_; i += 256) cfg[i] = configs[i];
    }
    __syncthreads();

    // ---- GEMM: mo[e][m] = sum_n xs[e][n] * wt[n][m] ------------------------
    {
        const int tx = tid & 15, ty = tid >> 4;
        const int e0 = ty * 8,  m0 = tx * 8;
        float acc[8][8];
        #pragma unroll
        for (int i = 0; i < 8; i++)
            #pragma unroll
            for (int j = 0; j < 8; j++) acc[i][j] = 0.f;

        for (int n = 0; n < NAO_; n += 4) {
            float4 xv[8];
            #pragma unroll
            for (int i = 0; i < 8; i++)
                xv[i] = *(const float4*)(xs + (e0 + i) * XS_STRIDE + n);
            #pragma unroll
            for (int nn = 0; nn < 4; nn++) {
                float4 w0 = *(const float4*)(wt + (n + nn) * WT_STRIDE + m0);
                float4 w1 = *(const float4*)(wt + (n + nn) * WT_STRIDE + m0 + 4);
                float wv[8] = {w0.x, w0.y, w0.z, w0.w, w1.x, w1.y, w1.z, w1.w};
                #pragma unroll
                for (int i = 0; i < 8; i++) {
                    float xvn = (nn == 0) ? xv[i].x : (nn == 1) ? xv[i].y
                              : (nn == 2) ? xv[i].z : xv[i].w;
                    #pragma unroll
                    for (int j = 0; j < 8; j++)
                        acc[i][j] = fmaf(xvn, wv[j], acc[i][j]);
                }
            }
        }
        #pragma unroll
        for (int i = 0; i < 8; i++)
            #pragma unroll
            for (int j = 0; j < 8; j++)
                mo[(e0 + i) * MO_STRIDE + (m0 + j)] = acc[i][j];
    }
    __syncthreads();

    // ---- 32 determinants: 1 warp per 64x64 matrix, register-resident LU ----
    // Lane l owns rows l (a[]) and l+32 (bb[]). Partial pivoting without
    // physical swaps: pivot rows are marked eliminated; the permutation sign
    // is recovered from the inversion count of the pivot-row sequence.
    const int w    = tid >> 5;
    const int lane = tid & 31;

    for (int r = 0; r < 4; r++) {
        const int  c  = r * 8 + w;
        const int* cf = cfg + c * DD_;
        const int  rA = cf[lane]      * MO_STRIDE;
        const int  rB = cf[lane + 32] * MO_STRIDE;

        float a[DD_], bb[DD_];
        #pragma unroll
        for (int j = 0; j < DD_; j++) {
            const int cj = cf[j];              // broadcast load
            a[j]  = mo[rA + cj];
            bb[j] = mo[rB + cj];
        }

        bool e0f = false, e1f = false;
        float detp = 1.f;
        unsigned long long chosen = 0ull;
        int inv = 0;

        #pragma unroll
        for (int k = 0; k < DD_; k++) {
            // --- pivot search over uneliminated rows (warp argmax) ---
            float c0 = e0f ? -1.f : fabsf(a[k]);
            float c1 = e1f ? -1.f : fabsf(bb[k]);
            float best; int bid;
            if (c1 > c0) { best = c1; bid = lane + 32; }
            else         { best = c0; bid = lane; }
            #pragma unroll
            for (int off = 16; off; off >>= 1) {
                float ob = __shfl_xor_sync(0xffffffffu, best, off);
                int   oi = __shfl_xor_sync(0xffffffffu, bid,  off);
                // lexicographic total order -> all lanes converge identically
                if (ob > best || (ob == best && oi < bid)) { best = ob; bid = oi; }
            }
            const int  rl  = bid & 31;
            const bool rhi = bid >= 32;

            // pivot value from the owner lane
            float usk = rhi ? bb[k] : a[k];
            float p   = __shfl_sync(0xffffffffu, usk, rl);

            detp *= p;
            inv  += (int)__popcll((chosen >> bid) >> 1);   // #earlier pivots with larger row id
            chosen |= (1ull << bid);

            const float rp  = 1.f / p;                      // IEEE divide, once per step
            const float nm0 = -(a[k]  * rp);
            const float nm1 = -(bb[k] * rp);
            if (bid == lane)            e0f = true;
            else if (bid == lane + 32)  e1f = true;

            // --- rank-1 update of trailing columns ---
            #pragma unroll
            for (int j = k + 1; j < DD_; j++) {
                float us = rhi ? bb[j] : a[j];
                float u  = __shfl_sync(0xffffffffu, us, rl);
                a[j]  = fmaf(nm0, u, a[j]);
                bb[j] = fmaf(nm1, u, bb[j]);
            }
        }

        if (lane == 0) dets[c] = (inv & 1) ? -detp : detp;
    }
    __syncthreads();

    // ---- weighted reduction: out[b] = sum_c dets[c] * W_ci[0][c] ----------
    if (tid == 0) {
        float s = 0.f;
        #pragma unroll
        for (int c2 = 0; c2 < NC_; c2++) s += dets[c2] * W_ci[c2];
        out[b] = s;
    }
}

extern "C" void kernel_launch(void* const* d_in, const int* in_sizes, int n_in,
                              void* d_out, int out_size)
{
    const float* x       = (const float*)d_in[0];   // (1024,128,128) f32
    const float* W_mo    = (const float*)d_in[1];   // (128,128) f32
    const float* W_ci    = (const float*)d_in[2];   // (1,32)   f32
    const int*   configs = (const int*)  d_in[3];   // (32,64)  i32
    float*       out     = (float*)d_out;           // (1024,1) f32

    cudaFuncSetAttribute(wavenet_det_kernel,
                         cudaFuncAttributeMaxDynamicSharedMemorySize, SMEM_BYTES);
    wavenet_det_kernel<<<NB_, 256, SMEM_BYTES>>>(x, W_mo, W_ci, configs, out);
}

// round 14
// speedup vs baseline: 1.0007x; 1.0007x over previous
#include <cuda_runtime.h>

// Problem constants
#define NB_   1024
#define NE_   128
#define NAO_  128
#define NMO_  128
#define NC_   32
#define DD_   64

// smem strides (in floats) chosen for alignment + bank behavior
#define XS_STRIDE 128   // x tile, float4 loads, broadcast access -> no pad needed
#define WT_STRIDE 132   // transposed W, float4 aligned (132 % 4 == 0)
#define MO_STRIDE 130   // mo tile, even (float2-capable), mild conflicts on gather

// floats: xs 128*128=16384, wt 128*132=16896, mo 128*130=16640,
//         cfg (as int) 32*64=2048, dets 32   => 52000 floats = 208000 bytes
#define SMEM_BYTES (52000 * 4)

__global__ __launch_bounds__(256, 1)
void wavenet_det_kernel(const float* __restrict__ x,
                        const float* __restrict__ W_mo,
                        const float* __restrict__ W_ci,
                        const int*   __restrict__ configs,
                        float*       __restrict__ out)
{
    extern __shared__ float sm[];
    float* xs   = sm;                               // [128][128]
    float* wt   = xs + NE_ * XS_STRIDE;             // [n][m] transposed W, [128][132]
    float* mo   = wt + NAO_ * WT_STRIDE;            // [e][m], [128][130]
    int*   cfg  = (int*)(mo + NE_ * MO_STRIDE);     // [32][64]
    float* dets = (float*)(cfg + NC_ * DD_);        // [32]

    const int tid = threadIdx.x;
    const int b   = blockIdx.x;

    // ---- stage inputs ------------------------------------------------------
    {
        const float4* xb4 = (const float4*)(x + (size_t)b * NE_ * NAO_);
        float4* xs4 = (float4*)xs;
        #pragma unroll 4
        for (int i = tid; i < NE_ * NAO_ / 4; i += 256) xs4[i] = xb4[i];

        // transposed W: wt[n][m] = W_mo[m][n]   (coalesced global reads)
        for (int i = tid; i < NMO_ * NAO_; i += 256) {
            int m = i >> 7, n = i & 127;
            wt[n * WT_STRIDE + m] = W_mo[i];
        }
        for (int i = tid; i < NC_ * DD_; i += 256) cfg[i] = configs[i];
    }
    __syncthreads();

    // ---- GEMM: mo[e][m] = sum_n xs[e][n] * wt[n][m] ------------------------
    {
        const int tx = tid & 15, ty = tid >> 4;
        const int e0 = ty * 8,  m0 = tx * 8;
        float acc[8][8];
        #pragma unroll
        for (int i = 0; i < 8; i++)
            #pragma unroll
            for (int j = 0; j < 8; j++) acc[i][j] = 0.f;

        for (int n = 0; n < NAO_; n += 4) {
            float4 xv[8];
            #pragma unroll
            for (int i = 0; i < 8; i++)
                xv[i] = *(const float4*)(xs + (e0 + i) * XS_STRIDE + n);
            #pragma unroll
            for (int nn = 0; nn < 4; nn++) {
                float4 w0 = *(const float4*)(wt + (n + nn) * WT_STRIDE + m0);
                float4 w1 = *(const float4*)(wt + (n + nn) * WT_STRIDE + m0 + 4);
                float wv[8] = {w0.x, w0.y, w0.z, w0.w, w1.x, w1.y, w1.z, w1.w};
                #pragma unroll
                for (int i = 0; i < 8; i++) {
                    float xvn = (nn == 0) ? xv[i].x : (nn == 1) ? xv[i].y
                              : (nn == 2) ? xv[i].z : xv[i].w;
                    #pragma unroll
                    for (int j = 0; j < 8; j++)
                        acc[i][j] = fmaf(xvn, wv[j], acc[i][j]);
                }
            }
        }
        #pragma unroll
        for (int i = 0; i < 8; i++)
            #pragma unroll
            for (int j = 0; j < 8; j++)
                mo[(e0 + i) * MO_STRIDE + (m0 + j)] = acc[i][j];
    }
    __syncthreads();

    // ---- 32 determinants: 1 warp per 64x64 matrix, register-resident LU ----
    // Lane l owns rows l (a[]) and l+32 (bb[]). Partial pivoting without
    // physical swaps: pivot rows are marked eliminated; the permutation sign
    // is recovered from the inversion count of the pivot-row sequence.
    const int w    = tid >> 5;
    const int lane = tid & 31;

    for (int r = 0; r < 4; r++) {
        const int  c  = r * 8 + w;
        const int* cf = cfg + c * DD_;
        const int  rA = cf[lane]      * MO_STRIDE;
        const int  rB = cf[lane + 32] * MO_STRIDE;

        float a[DD_], bb[DD_];
        #pragma unroll
        for (int j = 0; j < DD_; j++) {
            const int cj = cf[j];              // broadcast load
            a[j]  = mo[rA + cj];
            bb[j] = mo[rB + cj];
        }

        bool e0f = false, e1f = false;
        float detp = 1.f;
        unsigned long long chosen = 0ull;
        int inv = 0;

        #pragma unroll
        for (int k = 0; k < DD_; k++) {
            // --- pivot search over uneliminated rows (warp argmax) ---
            float c0 = e0f ? -1.f : fabsf(a[k]);
            float c1 = e1f ? -1.f : fabsf(bb[k]);
            float best; int bid;
            if (c1 > c0) { best = c1; bid = lane + 32; }
            else         { best = c0; bid = lane; }
            #pragma unroll
            for (int off = 16; off; off >>= 1) {
                float ob = __shfl_xor_sync(0xffffffffu, best, off);
                int   oi = __shfl_xor_sync(0xffffffffu, bid,  off);
                // lexicographic total order -> all lanes converge identically
                if (ob > best || (ob == best && oi < bid)) { best = ob; bid = oi; }
            }
            const int  rl  = bid & 31;
            const bool rhi = bid >= 32;

            // pivot value from the owner lane
            float usk = rhi ? bb[k] : a[k];
            float p   = __shfl_sync(0xffffffffu, usk, rl);

            detp *= p;
            inv  += (int)__popcll((chosen >> bid) >> 1);   // #earlier pivots with larger row id
            chosen |= (1ull << bid);

            const float rp  = 1.f / p;                      // IEEE divide, once per step
            const float nm0 = -(a[k]  * rp);
            const float nm1 = -(bb[k] * rp);
            if (bid == lane)            e0f = true;
            else if (bid == lane + 32)  e1f = true;

            // --- rank-1 update of trailing columns ---
            #pragma unroll
            for (int j = k + 1; j < DD_; j++) {
                float us = rhi ? bb[j] : a[j];
                float u  = __shfl_sync(0xffffffffu, us, rl);
                a[j]  = fmaf(nm0, u, a[j]);
                bb[j] = fmaf(nm1, u, bb[j]);
            }
        }

        if (lane == 0) dets[c] = (inv & 1) ? -detp : detp;
    }
    __syncthreads();

    // ---- weighted reduction: out[b] = sum_c dets[c] * W_ci[0][c] ----------
    if (tid == 0) {
        float s = 0.f;
        #pragma unroll
        for (int c2 = 0; c2 < NC_; c2++) s += dets[c2] * W_ci[c2];
        out[b] = s;
    }
}

extern "C" void kernel_launch(void* const* d_in, const int* in_sizes, int n_in,
                              void* d_out, int out_size)
{
    const float* x       = (const float*)d_in[0];   // (1024,128,128) f32
    const float* W_mo    = (const float*)d_in[1];   // (128,128) f32
    const float* W_ci    = (const float*)d_in[2];   // (1,32)   f32
    const int*   configs = (const int*)  d_in[3];   // (32,64)  i32
    float*       out     = (float*)d_out;           // (1024,1) f32

    cudaFuncSetAttribute(wavenet_det_kernel,
                         cudaFuncAttributeMaxDynamicSharedMemorySize, SMEM_BYTES);
    wavenet_det_kernel<<<NB_, 256, SMEM_BYTES>>>(x, W_mo, W_ci, configs, out);
}

// round 15
// speedup vs baseline: 1.0014x; 1.0006x over previous
#include <cuda_runtime.h>

// Problem constants
#define NB_   1024
#define NE_   128
#define NAO_  128
#define NMO_  128
#define NC_   32
#define DD_   64

// smem strides (in floats) chosen for alignment + bank behavior
#define XS_STRIDE 128   // x tile, float4 loads, broadcast access -> no pad needed
#define WT_STRIDE 132   // transposed W, float4 aligned (132 % 4 == 0)
#define MO_STRIDE 130   // mo tile, even (float2-capable), mild conflicts on gather

// floats: xs 128*128=16384, wt 128*132=16896, mo 128*130=16640,
//         cfg (as int) 32*64=2048, dets 32   => 52000 floats = 208000 bytes
#define SMEM_BYTES (52000 * 4)

__global__ __launch_bounds__(256, 1)
void wavenet_det_kernel(const float* __restrict__ x,
                        const float* __restrict__ W_mo,
                        const float* __restrict__ W_ci,
                        const int*   __restrict__ configs,
                        float*       __restrict__ out)
{
    extern __shared__ float sm[];
    float* xs   = sm;                               // [128][128]
    float* wt   = xs + NE_ * XS_STRIDE;             // [n][m] transposed W, [128][132]
    float* mo   = wt + NAO_ * WT_STRIDE;            // [e][m], [128][130]
    int*   cfg  = (int*)(mo + NE_ * MO_STRIDE);     // [32][64]
    float* dets = (float*)(cfg + NC_ * DD_);        // [32]

    const int tid = threadIdx.x;
    const int b   = blockIdx.x;

    // ---- stage inputs ------------------------------------------------------
    {
        const float4* xb4 = (const float4*)(x + (size_t)b * NE_ * NAO_);
        float4* xs4 = (float4*)xs;
        #pragma unroll 4
        for (int i = tid; i < NE_ * NAO_ / 4; i += 256) xs4[i] = xb4[i];

        // transposed W: wt[n][m] = W_mo[m][n]   (coalesced global reads)
        for (int i = tid; i < NMO_ * NAO_; i += 256) {
            int m = i >> 7, n = i & 127;
            wt[n * WT_STRIDE + m] = W_mo[i];
        }
        for (int i = tid; i < NC_ * DD_; i += 256) cfg[i] = configs[i];
    }
    __syncthreads();

    // ---- GEMM: mo[e][m] = sum_n xs[e][n] * wt[n][m] ------------------------
    {
        const int tx = tid & 15, ty = tid >> 4;
        const int e0 = ty * 8,  m0 = tx * 8;
        float acc[8][8];
        #pragma unroll
        for (int i = 0; i < 8; i++)
            #pragma unroll
            for (int j = 0; j < 8; j++) acc[i][j] = 0.f;

        for (int n = 0; n < NAO_; n += 4) {
            float4 xv[8];
            #pragma unroll
            for (int i = 0; i < 8; i++)
                xv[i] = *(const float4*)(xs + (e0 + i) * XS_STRIDE + n);
            #pragma unroll
            for (int nn = 0; nn < 4; nn++) {
                float4 w0 = *(const float4*)(wt + (n + nn) * WT_STRIDE + m0);
                float4 w1 = *(const float4*)(wt + (n + nn) * WT_STRIDE + m0 + 4);
                float wv[8] = {w0.x, w0.y, w0.z, w0.w, w1.x, w1.y, w1.z, w1.w};
                #pragma unroll
                for (int i = 0; i < 8; i++) {
                    float xvn = (nn == 0) ? xv[i].x : (nn == 1) ? xv[i].y
                              : (nn == 2) ? xv[i].z : xv[i].w;
                    #pragma unroll
                    for (int j = 0; j < 8; j++)
                        acc[i][j] = fmaf(xvn, wv[j], acc[i][j]);
                }
            }
        }
        #pragma unroll
        for (int i = 0; i < 8; i++)
            #pragma unroll
            for (int j = 0; j < 8; j++)
                mo[(e0 + i) * MO_STRIDE + (m0 + j)] = acc[i][j];
    }
    __syncthreads();

    // ---- 32 determinants: 1 warp per 64x64 matrix, register-resident LU ----
    // Lane l owns rows l (a[]) and l+32 (bb[]). Partial pivoting without
    // physical swaps: pivot rows are marked eliminated; the permutation sign
    // is recovered from the inversion count of the pivot-row sequence.
    const int w    = tid >> 5;
    const int lane = tid & 31;

    for (int r = 0; r < 4; r++) {
        const int  c  = r * 8 + w;
        const int* cf = cfg + c * DD_;
        const int  rA = cf[lane]      * MO_STRIDE;
        const int  rB = cf[lane + 32] * MO_STRIDE;

        float a[DD_], bb[DD_];
        #pragma unroll
        for (int j = 0; j < DD_; j++) {
            const int cj = cf[j];              // broadcast load
            a[j]  = mo[rA + cj];
            bb[j] = mo[rB + cj];
        }

        bool e0f = false, e1f = false;
        float detp = 1.f;
        unsigned long long chosen = 0ull;
        int inv = 0;

        #pragma unroll
        for (int k = 0; k < DD_; k++) {
            // --- pivot search over uneliminated rows (warp argmax) ---
            float c0 = e0f ? -1.f : fabsf(a[k]);
            float c1 = e1f ? -1.f : fabsf(bb[k]);
            float best; int bid;
            if (c1 > c0) { best = c1; bid = lane + 32; }
            else         { best = c0; bid = lane; }
            #pragma unroll
            for (int off = 16; off; off >>= 1) {
                float ob = __shfl_xor_sync(0xffffffffu, best, off);
                int   oi = __shfl_xor_sync(0xffffffffu, bid,  off);
                // lexicographic total order -> all lanes converge identically
                if (ob > best || (ob == best && oi < bid)) { best = ob; bid = oi; }
            }
            const int  rl  = bid & 31;
            const bool rhi = bid >= 32;

            // pivot value from the owner lane
            float usk = rhi ? bb[k] : a[k];
            float p   = __shfl_sync(0xffffffffu, usk, rl);

            detp *= p;
            inv  += (int)__popcll((chosen >> bid) >> 1);   // #earlier pivots with larger row id
            chosen |= (1ull << bid);

            const float rp  = 1.f / p;                      // IEEE divide, once per step
            const float nm0 = -(a[k]  * rp);
            const float nm1 = -(bb[k] * rp);
            if (bid == lane)            e0f = true;
            else if (bid == lane + 32)  e1f = true;

            // --- rank-1 update of trailing columns ---
            #pragma unroll
            for (int j = k + 1; j < DD_; j++) {
                float us = rhi ? bb[j] : a[j];
                float u  = __shfl_sync(0xffffffffu, us, rl);
                a[j]  = fmaf(nm0, u, a[j]);
                bb[j] = fmaf(nm1, u, bb[j]);
            }
        }

        if (lane == 0) dets[c] = (inv & 1) ? -detp : detp;
    }
    __syncthreads();

    // ---- weighted reduction: out[b] = sum_c dets[c] * W_ci[0][c] ----------
    if (tid == 0) {
        float s = 0.f;
        #pragma unroll
        for (int c2 = 0; c2 < NC_; c2++) s += dets[c2] * W_ci[c2];
        out[b] = s;
    }
}

extern "C" void kernel_launch(void* const* d_in, const int* in_sizes, int n_in,
                              void* d_out, int out_size)
{
    const float* x       = (const float*)d_in[0];   // (1024,128,128) f32
    const float* W_mo    = (const float*)d_in[1];   // (128,128) f32
    const float* W_ci    = (const float*)d_in[2];   // (1,32)   f32
    const int*   configs = (const int*)  d_in[3];   // (32,64)  i32
    float*       out     = (float*)d_out;           // (1024,1) f32

    cudaFuncSetAttribute(wavenet_det_kernel,
                         cudaFuncAttributeMaxDynamicSharedMemorySize, SMEM_BYTES);
    wavenet_det_kernel<<<NB_, 256, SMEM_BYTES>>>(x, W_mo, W_ci, configs, out);
}

// round 16
// speedup vs baseline: 1.0023x; 1.0009x over previous
#include <cuda_runtime.h>

// Problem constants
#define NB_   1024
#define NE_   128
#define NAO_  128
#define NMO_  128
#define NC_   32
#define DD_   64

// smem strides (in floats) chosen for alignment + bank behavior
#define XS_STRIDE 128   // x tile, float4 loads, broadcast access -> no pad needed
#define WT_STRIDE 132   // transposed W, float4 aligned (132 % 4 == 0)
#define MO_STRIDE 130   // mo tile, even (float2-capable), mild conflicts on gather

// floats: xs 128*128=16384, wt 128*132=16896, mo 128*130=16640,
//         cfg (as int) 32*64=2048, dets 32   => 52000 floats = 208000 bytes
#define SMEM_BYTES (52000 * 4)

__global__ __launch_bounds__(256, 1)
void wavenet_det_kernel(const float* __restrict__ x,
                        const float* __restrict__ W_mo,
                        const float* __restrict__ W_ci,
                        const int*   __restrict__ configs,
                        float*       __restrict__ out)
{
    extern __shared__ float sm[];
    float* xs   = sm;                               // [128][128]
    float* wt   = xs + NE_ * XS_STRIDE;             // [n][m] transposed W, [128][132]
    float* mo   = wt + NAO_ * WT_STRIDE;            // [e][m], [128][130]
    int*   cfg  = (int*)(mo + NE_ * MO_STRIDE);     // [32][64]
    float* dets = (float*)(cfg + NC_ * DD_);        // [32]

    const int tid = threadIdx.x;
    const int b   = blockIdx.x;

    // ---- stage inputs ------------------------------------------------------
    {
        const float4* xb4 = (const float4*)(x + (size_t)b * NE_ * NAO_);
        float4* xs4 = (float4*)xs;
        #pragma unroll 4
        for (int i = tid; i < NE_ * NAO_ / 4; i += 256) xs4[i] = xb4[i];

        // transposed W: wt[n][m] = W_mo[m][n]   (coalesced global reads)
        for (int i = tid; i < NMO_ * NAO_; i += 256) {
            int m = i >> 7, n = i & 127;
            wt[n * WT_STRIDE + m] = W_mo[i];
        }
        for (int i = tid; i < NC_ * DD_; i += 256) cfg[i] = configs[i];
    }
    __syncthreads();

    // ---- GEMM: mo[e][m] = sum_n xs[e][n] * wt[n][m] ------------------------
    {
        const int tx = tid & 15, ty = tid >> 4;
        const int e0 = ty * 8,  m0 = tx * 8;
        float acc[8][8];
        #pragma unroll
        for (int i = 0; i < 8; i++)
            #pragma unroll
            for (int j = 0; j < 8; j++) acc[i][j] = 0.f;

        for (int n = 0; n < NAO_; n += 4) {
            float4 xv[8];
            #pragma unroll
            for (int i = 0; i < 8; i++)
                xv[i] = *(const float4*)(xs + (e0 + i) * XS_STRIDE + n);
            #pragma unroll
            for (int nn = 0; nn < 4; nn++) {
                float4 w0 = *(const float4*)(wt + (n + nn) * WT_STRIDE + m0);
                float4 w1 = *(const float4*)(wt + (n + nn) * WT_STRIDE + m0 + 4);
                float wv[8] = {w0.x, w0.y, w0.z, w0.w, w1.x, w1.y, w1.z, w1.w};
                #pragma unroll
                for (int i = 0; i < 8; i++) {
                    float xvn = (nn == 0) ? xv[i].x : (nn == 1) ? xv[i].y
                              : (nn == 2) ? xv[i].z : xv[i].w;
                    #pragma unroll
                    for (int j = 0; j < 8; j++)
                        acc[i][j] = fmaf(xvn, wv[j], acc[i][j]);
                }
            }
        }
        #pragma unroll
        for (int i = 0; i < 8; i++)
            #pragma unroll
            for (int j = 0; j < 8; j++)
                mo[(e0 + i) * MO_STRIDE + (m0 + j)] = acc[i][j];
    }
    __syncthreads();

    // ---- 32 determinants: 1 warp per 64x64 matrix, register-resident LU ----
    // Lane l owns rows l (a[]) and l+32 (bb[]). Partial pivoting without
    // physical swaps: pivot rows are marked eliminated; the permutation sign
    // is recovered from the inversion count of the pivot-row sequence.
    const int w    = tid >> 5;
    const int lane = tid & 31;

    for (int r = 0; r < 4; r++) {
        const int  c  = r * 8 + w;
        const int* cf = cfg + c * DD_;
        const int  rA = cf[lane]      * MO_STRIDE;
        const int  rB = cf[lane + 32] * MO_STRIDE;

        float a[DD_], bb[DD_];
        #pragma unroll
        for (int j = 0; j < DD_; j++) {
            const int cj = cf[j];              // broadcast load
            a[j]  = mo[rA + cj];
            bb[j] = mo[rB + cj];
        }

        bool e0f = false, e1f = false;
        float detp = 1.f;
        unsigned long long chosen = 0ull;
        int inv = 0;

        #pragma unroll
        for (int k = 0; k < DD_; k++) {
            // --- pivot search over uneliminated rows (warp argmax) ---
            float c0 = e0f ? -1.f : fabsf(a[k]);
            float c1 = e1f ? -1.f : fabsf(bb[k]);
            float best; int bid;
            if (c1 > c0) { best = c1; bid = lane + 32; }
            else         { best = c0; bid = lane; }
            #pragma unroll
            for (int off = 16; off; off >>= 1) {
                float ob = __shfl_xor_sync(0xffffffffu, best, off);
                int   oi = __shfl_xor_sync(0xffffffffu, bid,  off);
                // lexicographic total order -> all lanes converge identically
                if (ob > best || (ob == best && oi < bid)) { best = ob; bid = oi; }
            }
            const int  rl  = bid & 31;
            const bool rhi = bid >= 32;

            // pivot value from the owner lane
            float usk = rhi ? bb[k] : a[k];
            float p   = __shfl_sync(0xffffffffu, usk, rl);

            detp *= p;
            inv  += (int)__popcll((chosen >> bid) >> 1);   // #earlier pivots with larger row id
            chosen |= (1ull << bid);

            const float rp  = 1.f / p;                      // IEEE divide, once per step
            const float nm0 = -(a[k]  * rp);
            const float nm1 = -(bb[k] * rp);
            if (bid == lane)            e0f = true;
            else if (bid == lane + 32)  e1f = true;

            // --- rank-1 update of trailing columns ---
            #pragma unroll
            for (int j = k + 1; j < DD_; j++) {
                float us = rhi ? bb[j] : a[j];
                float u  = __shfl_sync(0xffffffffu, us, rl);
                a[j]  = fmaf(nm0, u, a[j]);
                bb[j] = fmaf(nm1, u, bb[j]);
            }
        }

        if (lane == 0) dets[c] = (inv & 1) ? -detp : detp;
    }
    __syncthreads();

    // ---- weighted reduction: out[b] = sum_c dets[c] * W_ci[0][c] ----------
    if (tid == 0) {
        float s = 0.f;
        #pragma unroll
        for (int c2 = 0; c2 < NC_; c2++) s += dets[c2] * W_ci[c2];
        out[b] = s;
    }
}

extern "C" void kernel_launch(void* const* d_in, const int* in_sizes, int n_in,
                              void* d_out, int out_size)
{
    const float* x       = (const float*)d_in[0];   // (1024,128,128) f32
    const float* W_mo    = (const float*)d_in[1];   // (128,128) f32
    const float* W_ci    = (const float*)d_in[2];   // (1,32)   f32
    const int*   configs = (const int*)  d_in[3];   // (32,64)  i32
    float*       out     = (float*)d_out;           // (1024,1) f32

    cudaFuncSetAttribute(wavenet_det_kernel,
                         cudaFuncAttributeMaxDynamicSharedMemorySize, SMEM_BYTES);
    wavenet_det_kernel<<<NB_, 256, SMEM_BYTES>>>(x, W_mo, W_ci, configs, out);
}